// round 4
// baseline (speedup 1.0000x reference)
#include <cuda_runtime.h>
#include <cstdint>
#include <cstddef>

#define BB   256
#define SS   512
#define IN   512
#define HH   1024
#define OUTD 3
#define BH   (BB * HH)          // 262144
#define XROW ((size_t)SS * IN)  // per-batch stride in x

// ---------------- small device scratch (6 MB total) ----------------
__device__ float g_r[4 * BH];   // per-step gate preactivations [gate][b][h]
__device__ float g_h[BH];       // current hidden state
__device__ float g_c[BH];       // current cell state
__device__ unsigned g_bar_count;   // zero-init; self-resetting
__device__ unsigned g_bar_sense;   // even #barriers/launch -> returns to 0

// ---------------- helpers ----------------
__device__ __forceinline__ float sigf(float x) {
    return 1.f / (1.f + expf(-x));
}

// Sense-reversing grid barrier. Release: all threads __threadfence() before
// arrive. Acquire: thread 0 __threadfence() after the spin (gpu-scope fence
// invalidates this SM's L1D so plain loads see other CTAs' writes).
// Replay-safe: even #barriers/launch -> sense ends at 0; count self-resets.
__device__ __forceinline__ void gridbar(unsigned& ls, unsigned nblocks) {
    ls ^= 1u;
    __threadfence();
    __syncthreads();
    if (threadIdx.x == 0) {
        unsigned v = atomicAdd(&g_bar_count, 1u);
        if (v == nblocks - 1u) {
            atomicExch(&g_bar_count, 0u);
            atomicExch(&g_bar_sense, ls);
        } else {
            while (*(volatile unsigned*)&g_bar_sense != ls) {}
        }
        __threadfence();
    }
    __syncthreads();
}

// Warp-collective out-projection + softmax for one batch row of g_h.
__device__ __forceinline__ void out_proj_warp(
    int b, int sidx,
    const float* __restrict__ Wout, const float* __restrict__ bout,
    float* __restrict__ out)
{
    const int lane = threadIdx.x & 31;
    float a0 = 0.f, a1 = 0.f, a2 = 0.f;
    const float* hrow = g_h + (size_t)b * HH;
#pragma unroll 8
    for (int j = 0; j < HH / 32; j++) {
        float hv = hrow[lane + 32 * j];
        const float* wr = Wout + (size_t)(lane + 32 * j) * OUTD;
        a0 = fmaf(hv, wr[0], a0);
        a1 = fmaf(hv, wr[1], a1);
        a2 = fmaf(hv, wr[2], a2);
    }
#pragma unroll
    for (int off = 16; off; off >>= 1) {
        a0 += __shfl_down_sync(0xffffffffu, a0, off);
        a1 += __shfl_down_sync(0xffffffffu, a1, off);
        a2 += __shfl_down_sync(0xffffffffu, a2, off);
    }
    if (lane == 0) {
        float s0 = a0 + bout[0], s1 = a1 + bout[1], s2 = a2 + bout[2];
        float m = fmaxf(s0, fmaxf(s1, s2));
        float e0 = expf(s0 - m), e1 = expf(s1 - m), e2 = expf(s2 - m);
        float inv = 1.f / (e0 + e1 + e2);
        size_t ob = ((size_t)b * SS + sidx) * OUTD;
        out[ob + 0] = e0 * inv; out[ob + 1] = e1 * inv; out[ob + 2] = e2 * inv;
    }
}

// ================= single persistent kernel =================
// 128 blocks x 256 threads, one block per SM (co-resident: 128 <= 148).
// GEMM role per block: gate = blk>>5, mtile = (blk>>3)&3 (64 batch rows),
// ntile = blk&7 (128 H cols). Per step:
//   phase 1: r[gate] = h_{s-1} @ Wh + x_s @ Wx + bias   (fused K = 1536)
//            (+ gate-0 blocks emit out-proj/softmax for step s-1)
//   barrier
//   phase 2: gates -> c,h update (2048 contiguous elems per block)
//   barrier
__global__ __launch_bounds__(256) void lstm_persistent_kernel(
    const float* __restrict__ x,
    const float* __restrict__ h0, const float* __restrict__ c0,
    const float* __restrict__ Whi, const float* __restrict__ Whf,
    const float* __restrict__ Whg, const float* __restrict__ Who,
    const float* __restrict__ Wxi, const float* __restrict__ Wxf,
    const float* __restrict__ Wxg, const float* __restrict__ Wxo,
    const float* __restrict__ bi,  const float* __restrict__ bf,
    const float* __restrict__ bg,  const float* __restrict__ bo,
    const float* __restrict__ Wout, const float* __restrict__ bout,
    float* __restrict__ out, int write_hc)
{
    const int tid = threadIdx.x;
    const int blk = blockIdx.x;
    const int gate  = blk >> 5;
    const int mtile = (blk >> 3) & 3;
    const int ntile = blk & 7;

    const float* Wh = (gate == 0) ? Whi : (gate == 1) ? Whf : (gate == 2) ? Whg : Who;
    const float* Wx = (gate == 0) ? Wxi : (gate == 1) ? Wxf : (gate == 2) ? Wxg : Wxo;
    const float* bias = (gate == 0) ? bi : (gate == 1) ? bf : (gate == 2) ? bg : bo;
    float* rg = g_r + (size_t)gate * BH;

    const int m0 = mtile * 64;
    const int n0 = ntile * 128;

    __shared__ float as_[32][64];    // [k][m]
    __shared__ float ws[32][128];    // [k][n]

    const int ra = (tid >> 4) * 4;   // 0..60
    const int ca = (tid & 15) * 4;   // 0..60 (+64 for second half)

    float4 bj0 = *(const float4*)&bias[n0 + ca];
    float4 bj1 = *(const float4*)&bias[n0 + ca + 64];

    unsigned ls = 0;

    for (int s = 0; s < SS; s++) {
        // out-projection for the PREVIOUS step (gate-0 blocks; 8 warps = 8 batches)
        if (s > 0 && gate == 0) {
            int b = blk * 8 + (tid >> 5);
            out_proj_warp(b, s - 1, Wout, bout, out);
        }

        // ---- phase 1: fused GEMM (K = 1024 over h, then 512 over x_s) ----
        const float* hsrc = (s == 0) ? h0 : g_h;
        float acc[32];
#pragma unroll
        for (int q = 0; q < 32; q++) acc[q] = 0.f;

        for (int kb = 0; kb < 48; kb++) {
            const float* asrc;
            const float* wsrc;
            size_t arow;
            int kcol;
            if (kb < 32) {                       // recurrent part
                asrc = hsrc; arow = HH; kcol = kb * 32; wsrc = Wh;
            } else {                             // input part
                asrc = x + (size_t)s * IN; arow = XROW; kcol = (kb - 32) * 32; wsrc = Wx;
            }
            // A tile: 64 rows x 32 k -> transposed into as_[k][m]
#pragma unroll
            for (int it = 0; it < 2; it++) {
                int id = tid + it * 256;
                int r = id >> 3;
                int c = (id & 7) * 4;
                float4 v = *(const float4*)&asrc[(size_t)(m0 + r) * arow + kcol + c];
                as_[c + 0][r] = v.x; as_[c + 1][r] = v.y;
                as_[c + 2][r] = v.z; as_[c + 3][r] = v.w;
            }
            // W tile: 32 k x 128 n
#pragma unroll
            for (int it = 0; it < 4; it++) {
                int id = tid + it * 256;
                int r = id >> 5;
                int c = (id & 31) * 4;
                *(float4*)&ws[r][c] = *(const float4*)&wsrc[(size_t)(kcol + r) * HH + n0 + c];
            }
            __syncthreads();
#pragma unroll
            for (int kk = 0; kk < 32; kk++) {
                float4 a  = *(const float4*)&as_[kk][ra];
                float4 b0 = *(const float4*)&ws[kk][ca];
                float4 b1 = *(const float4*)&ws[kk][ca + 64];
                float av[4] = {a.x, a.y, a.z, a.w};
                float bv[8] = {b0.x, b0.y, b0.z, b0.w, b1.x, b1.y, b1.z, b1.w};
#pragma unroll
                for (int i = 0; i < 4; i++)
#pragma unroll
                    for (int j = 0; j < 8; j++)
                        acc[i * 8 + j] = fmaf(av[i], bv[j], acc[i * 8 + j]);
            }
            __syncthreads();
        }

        // epilogue: + bias, store to g_r
#pragma unroll
        for (int i = 0; i < 4; i++) {
            size_t pbase = (size_t)(m0 + ra + i) * HH + n0;
            float4 o0, o1;
            o0.x = acc[i * 8 + 0] + bj0.x; o0.y = acc[i * 8 + 1] + bj0.y;
            o0.z = acc[i * 8 + 2] + bj0.z; o0.w = acc[i * 8 + 3] + bj0.w;
            o1.x = acc[i * 8 + 4] + bj1.x; o1.y = acc[i * 8 + 5] + bj1.y;
            o1.z = acc[i * 8 + 6] + bj1.z; o1.w = acc[i * 8 + 7] + bj1.w;
            *(float4*)&rg[pbase + ca] = o0;
            *(float4*)&rg[pbase + ca + 64] = o1;
        }

        gridbar(ls, gridDim.x);   // barrier 1

        // ---- phase 2: gates, c/h update (2048 contiguous elems per block) ----
        {
            size_t e0 = (size_t)blk * 2048 + (size_t)tid * 8;
#pragma unroll
            for (int v = 0; v < 2; v++) {
                size_t e = e0 + (size_t)v * 4;
                float4 ri  = *(const float4*)&g_r[e];
                float4 rf  = *(const float4*)&g_r[BH + e];
                float4 rg4 = *(const float4*)&g_r[2 * BH + e];
                float4 ro  = *(const float4*)&g_r[3 * BH + e];
                float4 cv  = (s == 0) ? *(const float4*)&c0[e] : *(const float4*)&g_c[e];
                float4 cn, hn;
                {
                    float iv = sigf(ri.x), fv = sigf(rf.x), gv = tanhf(rg4.x), ov = sigf(ro.x);
                    cn.x = fv * cv.x + iv * gv; hn.x = ov * tanhf(cn.x);
                }
                {
                    float iv = sigf(ri.y), fv = sigf(rf.y), gv = tanhf(rg4.y), ov = sigf(ro.y);
                    cn.y = fv * cv.y + iv * gv; hn.y = ov * tanhf(cn.y);
                }
                {
                    float iv = sigf(ri.z), fv = sigf(rf.z), gv = tanhf(rg4.z), ov = sigf(ro.z);
                    cn.z = fv * cv.z + iv * gv; hn.z = ov * tanhf(cn.z);
                }
                {
                    float iv = sigf(ri.w), fv = sigf(rf.w), gv = tanhf(rg4.w), ov = sigf(ro.w);
                    cn.w = fv * cv.w + iv * gv; hn.w = ov * tanhf(cn.w);
                }
                *(float4*)&g_c[e] = cn;
                *(float4*)&g_h[e] = hn;
            }
        }

        gridbar(ls, gridDim.x);   // barrier 2  (total 1024/launch -> even)
    }

    // final out-projection for s = SS-1 (g_h final after last barrier)
    if (gate == 0) {
        int b = blk * 8 + (tid >> 5);
        out_proj_warp(b, SS - 1, Wout, bout, out);
    }

    // final (h, c) outputs
    if (write_hc) {
        float* oh = out + (size_t)BB * SS * OUTD;
        float* oc = oh + BH;
        size_t e0 = (size_t)blk * 2048 + (size_t)tid * 8;
#pragma unroll
        for (int v = 0; v < 2; v++) {
            size_t e = e0 + (size_t)v * 4;
            *(float4*)&oh[e] = *(const float4*)&g_h[e];
            *(float4*)&oc[e] = *(const float4*)&g_c[e];
        }
    }
}

// ================= launch =================
extern "C" void kernel_launch(void* const* d_in, const int* in_sizes, int n_in,
                              void* d_out, int out_size)
{
    const float* x    = (const float*)d_in[0];
    const float* h0   = (const float*)d_in[1];
    const float* c0   = (const float*)d_in[2];
    const float* Xi   = (const float*)d_in[3];
    const float* Hi   = (const float*)d_in[4];
    const float* bi   = (const float*)d_in[5];
    const float* Xf   = (const float*)d_in[6];
    const float* Hf   = (const float*)d_in[7];
    const float* bf   = (const float*)d_in[8];
    const float* Xg   = (const float*)d_in[9];
    const float* Hg   = (const float*)d_in[10];
    const float* bg   = (const float*)d_in[11];
    const float* Xo   = (const float*)d_in[12];
    const float* Ho   = (const float*)d_in[13];
    const float* bo   = (const float*)d_in[14];
    const float* Wout = (const float*)d_in[15];
    const float* bout = (const float*)d_in[16];
    float* out = (float*)d_out;

    const int write_hc = (out_size >= BB * SS * OUTD + 2 * BH) ? 1 : 0;

    lstm_persistent_kernel<<<128, 256>>>(x, h0, c0,
                                         Hi, Hf, Hg, Ho,
                                         Xi, Xf, Xg, Xo,
                                         bi, bf, bg, bo,
                                         Wout, bout, out, write_hc);
}

// round 7
// speedup vs baseline: 1.6121x; 1.6121x over previous
#include <cuda_runtime.h>
#include <cstdint>
#include <cstddef>

#define BB 256
#define SS 512
#define IN 512
#define HH 1024
#define OUTD 3
#define BH (BB*HH)
#define XROW ((size_t)SS*IN)
#define NCH 48
#define NSLOT (4*8*NCH*4*16*32)

__device__ float g_r[4*BH];
__device__ float g_h[BH];
__device__ float g_c[BH];
__device__ float2 g_wpack[NSLOT];     // 25MB, tf32 bit patterns, B-fragment order
__device__ unsigned g_bar_count, g_bar_sense;

__device__ __forceinline__ float sigf(float x){ return 1.f/(1.f+expf(-x)); }
__device__ __forceinline__ uint32_t f2tf(float f){
    uint32_t r; asm("cvt.rna.tf32.f32 %0,%1;":"=r"(r):"f"(f)); return r;
}

__device__ __forceinline__ void gridbar(unsigned& ls){
    ls ^= 1u; __threadfence(); __syncthreads();
    if (threadIdx.x == 0) {
        unsigned v = atomicAdd(&g_bar_count,1u);
        if (v == 127u) { atomicExch(&g_bar_count,0u); atomicExch(&g_bar_sense,ls); }
        else { while (*(volatile unsigned*)&g_bar_sense != ls) {} }
        __threadfence();
    }
    __syncthreads();
}

__device__ __forceinline__ void out_proj_warp(
    int b,int sidx,const float*__restrict__ Wout,const float*__restrict__ bout,
    float*__restrict__ out)
{
    const int lane = threadIdx.x & 31;
    float a0=0.f,a1=0.f,a2=0.f;
    const float* hrow = g_h + (size_t)b*HH;
#pragma unroll 8
    for (int j=0;j<HH/32;j++){
        float hv = hrow[lane+32*j];
        const float* wr = Wout + (size_t)(lane+32*j)*OUTD;
        a0=fmaf(hv,wr[0],a0); a1=fmaf(hv,wr[1],a1); a2=fmaf(hv,wr[2],a2);
    }
#pragma unroll
    for (int off=16;off;off>>=1){
        a0 += __shfl_down_sync(0xffffffffu,a0,off);
        a1 += __shfl_down_sync(0xffffffffu,a1,off);
        a2 += __shfl_down_sync(0xffffffffu,a2,off);
    }
    if (lane==0){
        float s0=a0+bout[0], s1=a1+bout[1], s2=a2+bout[2];
        float m=fmaxf(s0,fmaxf(s1,s2));
        float e0=expf(s0-m), e1=expf(s1-m), e2=expf(s2-m);
        float inv=1.f/(e0+e1+e2);
        size_t ob=((size_t)b*SS+sidx)*OUTD;
        out[ob]=e0*inv; out[ob+1]=e1*inv; out[ob+2]=e2*inv;
    }
}

// -------- one-shot weight packer: [gate][ntb][ch][kt][nt][lane] -> (B[k][n],B[k+4][n]) tf32
__global__ __launch_bounds__(256) void pack_w(
    const float*__restrict__ Whi,const float*__restrict__ Whf,
    const float*__restrict__ Whg,const float*__restrict__ Who,
    const float*__restrict__ Wxi,const float*__restrict__ Wxf,
    const float*__restrict__ Wxg,const float*__restrict__ Wxo)
{
    for (int slot = blockIdx.x*256+threadIdx.x; slot < NSLOT; slot += gridDim.x*256){
        int lane = slot&31, t = slot>>5;
        int nt = t&15; t >>= 4;
        int kt = t&3;  t >>= 2;
        int ch = t%NCH; t /= NCH;
        int ntb = t&7;
        int gate = t>>3;
        const float* Wh = (gate==0)?Whi:(gate==1)?Whf:(gate==2)?Whg:Who;
        const float* Wx = (gate==0)?Wxi:(gate==1)?Wxf:(gate==2)?Wxg:Wxo;
        const float* W; int kb;
        if (ch<32){ W=Wh; kb=ch*32; } else { W=Wx; kb=(ch-32)*32; }
        int k = kb + kt*8 + (lane&3);
        int n = ntb*128 + nt*8 + (lane>>2);
        float2 v;
        v.x = __uint_as_float(f2tf(W[(size_t)k*HH+n]));
        v.y = __uint_as_float(f2tf(W[(size_t)(k+4)*HH+n]));
        g_wpack[slot] = v;
    }
}

// -------- persistent tf32-MMA recurrence --------
// 128 blocks x 256 thr. gate=blk>>5, mtile=(blk>>3)&3 (m0, 64 rows), ntile=blk&7 (n0, 128 cols).
// warp w: mt=w>>1 (16 rows), nh=w&1 (8 n-tiles of 8).
__global__ __launch_bounds__(256) void lstm_mma(
    const float*__restrict__ x,
    const float*__restrict__ h0,const float*__restrict__ c0,
    const float*__restrict__ bi,const float*__restrict__ bf,
    const float*__restrict__ bg,const float*__restrict__ bo,
    const float*__restrict__ Wout,const float*__restrict__ bout,
    float*__restrict__ out,int write_hc)
{
    const int tid=threadIdx.x, blk=blockIdx.x;
    const int gate=blk>>5, mtile=(blk>>3)&3, ntile=blk&7;
    const int m0=mtile*64, n0=ntile*128;
    const int w=tid>>5, lane=tid&31;
    const int mt=w>>1, nh=w&1;
    const float* bias=(gate==0)?bi:(gate==1)?bf:(gate==2)?bg:bo;
    float* rg = g_r + (size_t)gate*BH;

    __shared__ float As[64*36];     // A[m][k], pad 36 -> conflict-free frag reads
    __shared__ float2 Bs[4*16*32];  // B frags [kt][nt][lane]

    float2 bias_r[8];
#pragma unroll
    for (int j=0;j<8;j++)
        bias_r[j] = *(const float2*)&bias[n0 + (nh*8+j)*8 + 2*(lane&3)];

    const float2* wpB = g_wpack + (size_t)(gate*8+ntile)*NCH*2048;
    const int mrow = mt*16 + (lane>>2);
    unsigned ls=0;

    for (int s=0;s<SS;s++){
        if (s>0 && w<2) out_proj_warp(blk*2+w, s-1, Wout, bout, out);

        float acc[8][4];
#pragma unroll
        for (int j=0;j<8;j++){ acc[j][0]=acc[j][1]=acc[j][2]=acc[j][3]=0.f; }

        for (int ch=0;ch<NCH;ch++){
            const float* asrc; size_t arow; int kcol;
            if (ch<32){ asrc=(s==0)?h0:g_h; arow=HH; kcol=ch*32; }
            else      { asrc=x+(size_t)s*IN; arow=XROW; kcol=(ch-32)*32; }
            __syncthreads();
            // stage A (convert to tf32 bits)
#pragma unroll
            for (int it=0;it<2;it++){
                int id=tid+it*256, r=id>>3, c=(id&7)*4;
                float4 v = *(const float4*)&asrc[(size_t)(m0+r)*arow + kcol + c];
                v.x=__uint_as_float(f2tf(v.x)); v.y=__uint_as_float(f2tf(v.y));
                v.z=__uint_as_float(f2tf(v.z)); v.w=__uint_as_float(f2tf(v.w));
                *(float4*)&As[r*36+c] = v;
            }
            // stage B (pure copy of packed frags)
            {
                const float4* src = (const float4*)(wpB + (size_t)ch*2048);
                float4* dst = (float4*)Bs;
#pragma unroll
                for (int it=0;it<4;it++) dst[tid+it*256] = src[tid+it*256];
            }
            __syncthreads();
#pragma unroll
            for (int kt=0;kt<4;kt++){
                int kcl = kt*8 + (lane&3);
                uint32_t a0=__float_as_uint(As[mrow*36+kcl]);
                uint32_t a1=__float_as_uint(As[(mrow+8)*36+kcl]);
                uint32_t a2=__float_as_uint(As[mrow*36+kcl+4]);
                uint32_t a3=__float_as_uint(As[(mrow+8)*36+kcl+4]);
                const float2* bp = Bs + (kt*16 + nh*8)*32 + lane;
#pragma unroll
                for (int j=0;j<8;j++){
                    float2 b = bp[j*32];
                    asm volatile(
                        "mma.sync.aligned.m16n8k8.row.col.f32.tf32.tf32.f32 "
                        "{%0,%1,%2,%3},{%4,%5,%6,%7},{%8,%9},{%0,%1,%2,%3};"
                        : "+f"(acc[j][0]),"+f"(acc[j][1]),"+f"(acc[j][2]),"+f"(acc[j][3])
                        : "r"(a0),"r"(a1),"r"(a2),"r"(a3),
                          "r"(__float_as_uint(b.x)),"r"(__float_as_uint(b.y)));
                }
            }
        }
        // epilogue: +bias -> g_r
        {
            int r0 = m0 + mrow, cB = 2*(lane&3);
#pragma unroll
            for (int j=0;j<8;j++){
                int n = n0 + (nh*8+j)*8 + cB;
                float2 v0, v1;
                v0.x=acc[j][0]+bias_r[j].x; v0.y=acc[j][1]+bias_r[j].y;
                v1.x=acc[j][2]+bias_r[j].x; v1.y=acc[j][3]+bias_r[j].y;
                *(float2*)&rg[(size_t)r0*HH+n] = v0;
                *(float2*)&rg[(size_t)(r0+8)*HH+n] = v1;
            }
        }

        gridbar(ls);

        // phase 2: gates -> c,h (2048 contiguous elems per block)
        {
            size_t e0 = (size_t)blk*2048 + (size_t)tid*8;
#pragma unroll
            for (int v=0;v<2;v++){
                size_t e = e0 + (size_t)v*4;
                float4 ri =*(const float4*)&g_r[e];
                float4 rf =*(const float4*)&g_r[BH+e];
                float4 rg4=*(const float4*)&g_r[2*BH+e];
                float4 ro =*(const float4*)&g_r[3*BH+e];
                float4 cv = (s==0)?*(const float4*)&c0[e]:*(const float4*)&g_c[e];
                float4 cn,hn;
                { float iv=sigf(ri.x),fv=sigf(rf.x),gv=tanhf(rg4.x),ov=sigf(ro.x);
                  cn.x=fv*cv.x+iv*gv; hn.x=ov*tanhf(cn.x); }
                { float iv=sigf(ri.y),fv=sigf(rf.y),gv=tanhf(rg4.y),ov=sigf(ro.y);
                  cn.y=fv*cv.y+iv*gv; hn.y=ov*tanhf(cn.y); }
                { float iv=sigf(ri.z),fv=sigf(rf.z),gv=tanhf(rg4.z),ov=sigf(ro.z);
                  cn.z=fv*cv.z+iv*gv; hn.z=ov*tanhf(cn.z); }
                { float iv=sigf(ri.w),fv=sigf(rf.w),gv=tanhf(rg4.w),ov=sigf(ro.w);
                  cn.w=fv*cv.w+iv*gv; hn.w=ov*tanhf(cn.w); }
                *(float4*)&g_c[e]=cn; *(float4*)&g_h[e]=hn;
            }
        }

        gridbar(ls);   // 1024 barriers/launch total -> even, replay-safe
    }

    if (w<2) out_proj_warp(blk*2+w, SS-1, Wout, bout, out);

    if (write_hc){
        float* oh = out + (size_t)BB*SS*OUTD;
        float* oc = oh + BH;
        size_t e0 = (size_t)blk*2048 + (size_t)tid*8;
#pragma unroll
        for (int v=0;v<2;v++){
            size_t e = e0 + (size_t)v*4;
            *(float4*)&oh[e] = *(const float4*)&g_h[e];
            *(float4*)&oc[e] = *(const float4*)&g_c[e];
        }
    }
}

extern "C" void kernel_launch(void* const* d_in, const int* in_sizes, int n_in,
                              void* d_out, int out_size)
{
    const float* x   =(const float*)d_in[0];
    const float* h0  =(const float*)d_in[1];
    const float* c0  =(const float*)d_in[2];
    const float* Xi  =(const float*)d_in[3];
    const float* Hi  =(const float*)d_in[4];
    const float* bi  =(const float*)d_in[5];
    const float* Xf  =(const float*)d_in[6];
    const float* Hf  =(const float*)d_in[7];
    const float* bf  =(const float*)d_in[8];
    const float* Xg  =(const float*)d_in[9];
    const float* Hg  =(const float*)d_in[10];
    const float* bg  =(const float*)d_in[11];
    const float* Xo  =(const float*)d_in[12];
    const float* Ho  =(const float*)d_in[13];
    const float* bo  =(const float*)d_in[14];
    const float* Wout=(const float*)d_in[15];
    const float* bout=(const float*)d_in[16];
    float* out=(float*)d_out;
    const int write_hc = (out_size >= BB*SS*OUTD + 2*BH) ? 1 : 0;

    pack_w<<<3072,256>>>(Hi,Hf,Hg,Ho,Xi,Xf,Xg,Xo);
    lstm_mma<<<128,256>>>(x,h0,c0,bi,bf,bg,bo,Wout,bout,out,write_hc);
}